// round 14
// baseline (speedup 1.0000x reference)
#include <cuda_runtime.h>
#include <cuda_bf16.h>

#define NMAX   50000
#define EMAX   800000
#define HID    64
#define INCH   16
#define GMAX   128

// ---------------- scratch (device globals) ----------------------------------
__device__ __align__(16) int   g_deg [NMAX];
__device__ __align__(16) int   g_off [NMAX + 1];
__device__ __align__(16) int   g_cur [NMAX];
__device__ __align__(16) int   g_csr [EMAX];
__device__ __align__(16) float g_dinv[NMAX];
__device__ __align__(16) float g_hs  [(size_t)NMAX * HID];  // layer-1 feats * dinv[src]
__device__ __align__(16) float g_hs2 [(size_t)NMAX * HID];  // layer-2 feats * dinv[src]
__device__ __align__(16) float g_pool[GMAX * HID];
__device__ __align__(16) float g_cnt [GMAX];

__device__ __forceinline__ void red_add_f(float* p, float v) {
    asm volatile("red.global.add.f32 [%0], %1;" :: "l"(p), "f"(v) : "memory");
}

// ---------------- k0: init ---------------------------------------------------
__global__ void k_init(int n) {
    int i = blockIdx.x * blockDim.x + threadIdx.x;
    if (i < n) g_deg[i] = 0;
    if (i < GMAX * HID) g_pool[i] = 0.0f;
    if (i < GMAX) g_cnt[i] = 0.0f;
}

// ---------------- k1: in-degree histogram ------------------------------------
__global__ void k_deg(const int* __restrict__ dst, int e) {
    int i = blockIdx.x * blockDim.x + threadIdx.x;
    if (i < e) atomicAdd(&g_deg[dst[i]], 1);
}

// ---------------- k2: exclusive scan (single block, 1024 threads) -------------
__global__ void k_scan(int n) {
    __shared__ int part[1024];
    int tid = threadIdx.x;
    int per = (n + 1023) / 1024;
    int start = tid * per;
    int end = start + per; if (end > n) end = n;
    int s = 0;
    for (int i = start; i < end; i++) s += g_deg[i];
    part[tid] = s;
    __syncthreads();
    for (int off = 1; off < 1024; off <<= 1) {
        int v = (tid >= off) ? part[tid - off] : 0;
        __syncthreads();
        part[tid] += v;
        __syncthreads();
    }
    int run = (tid > 0) ? part[tid - 1] : 0;
    for (int i = start; i < end; i++) {
        g_off[i] = run;
        g_cur[i] = run;
        run += g_deg[i];
    }
    if (tid == 1023) g_off[n] = run;
}

// ---------------- k3: CSR fill -------------------------------------------------
__global__ void k_fill(const int* __restrict__ src, const int* __restrict__ dst, int e) {
    int i = blockIdx.x * blockDim.x + threadIdx.x;
    if (i < e) {
        int pos = atomicAdd(&g_cur[dst[i]], 1);
        g_csr[pos] = src[i];
    }
}

// ---------------- k4: dinv + hs = (x@W1)*dinv ---------------------------------
__global__ void k_lin1(const float* __restrict__ x, const float* __restrict__ W1, int n) {
    __shared__ float Ws[INCH * HID];
    __shared__ float xs[4][INCH];
    __shared__ float ds[4];
    int tid = threadIdx.x;
    for (int i = tid; i < INCH * HID; i += 256) Ws[i] = W1[i];
    int node0 = blockIdx.x * 4;
    if (tid < 4 * INCH) {
        int nl = tid >> 4, k = tid & 15;
        int node = node0 + nl;
        xs[nl][k] = (node < n) ? x[(size_t)node * INCH + k] : 0.0f;
    }
    if (tid < 4) {
        int node = node0 + tid;
        float d = 0.0f;
        if (node < n) {
            d = rsqrtf((float)(g_deg[node] + 1));   // +1 self loop
            g_dinv[node] = d;
        }
        ds[tid] = d;
    }
    __syncthreads();
    int nl = tid >> 6, ch = tid & 63;
    int node = node0 + nl;
    if (node < n) {
        float s = 0.0f;
        #pragma unroll
        for (int k = 0; k < INCH; k++) s += xs[nl][k] * Ws[k * HID + ch];
        g_hs[(size_t)node * HID + ch] = s * ds[nl];
    }
}

// ---------------- k5: gather layer1 + relu + @W2 (fused) -----------------------
// block = 256 threads (4 nodes x 64 ch), loops over 8 groups -> 32 nodes/block
#define GROUPS 8
__global__ void k_gather_lin2(const float* __restrict__ W2, const float* __restrict__ b1, int n) {
    __shared__ float Ws[HID * HID];   // 16 KB
    __shared__ float zs[4][HID];
    int tid = threadIdx.x;
    for (int i = tid; i < HID * HID; i += 256) Ws[i] = W2[i];
    int nl = tid >> 6, ch = tid & 63;
    int block0 = blockIdx.x * (4 * GROUPS);
    for (int grp = 0; grp < GROUPS; grp++) {
        int node = block0 + grp * 4 + nl;
        float z = 0.0f;
        if (node < n) {
            int r0 = g_off[node], r1 = g_off[node + 1];
            float a0 = 0.0f, a1 = 0.0f;
            int j = r0;
            for (; j + 1 < r1; j += 2) {
                int s0 = g_csr[j], s1 = g_csr[j + 1];
                a0 += g_hs[(size_t)s0 * HID + ch];
                a1 += g_hs[(size_t)s1 * HID + ch];
            }
            if (j < r1) a0 += g_hs[(size_t)g_csr[j] * HID + ch];
            float agg = a0 + a1 + g_hs[(size_t)node * HID + ch];  // + self loop
            z = fmaxf(agg * g_dinv[node] + b1[ch], 0.0f);
        }
        __syncthreads();
        zs[nl][ch] = z;
        __syncthreads();
        if (node < n) {
            float s = 0.0f;
            #pragma unroll
            for (int k = 0; k < HID; k++) s += zs[nl][k] * Ws[k * HID + ch];
            g_hs2[(size_t)node * HID + ch] = s * g_dinv[node];
        }
    }
}

// ---------------- k6: gather layer2 + relu + pool (fused) ----------------------
__global__ void k_gather_pool(const float* __restrict__ b2,
                              const int* __restrict__ batch, int n) {
    int tid = threadIdx.x;
    int nl = tid >> 6, ch = tid & 63;
    int node = blockIdx.x * 4 + nl;
    if (node >= n) return;
    int r0 = g_off[node], r1 = g_off[node + 1];
    float a0 = 0.0f, a1 = 0.0f;
    int j = r0;
    for (; j + 1 < r1; j += 2) {
        int s0 = g_csr[j], s1 = g_csr[j + 1];
        a0 += g_hs2[(size_t)s0 * HID + ch];
        a1 += g_hs2[(size_t)s1 * HID + ch];
    }
    if (j < r1) a0 += g_hs2[(size_t)g_csr[j] * HID + ch];
    float agg = a0 + a1 + g_hs2[(size_t)node * HID + ch];
    float z = fmaxf(agg * g_dinv[node] + b2[ch], 0.0f);
    int g = __ldg(&batch[node]);
    red_add_f(&g_pool[g * HID + ch], z);
    if (ch == 0) red_add_f(&g_cnt[g], 1.0f);
}

// ---------------- k7: classifier ------------------------------------------------
__global__ void k_cls(const float* __restrict__ Wc, const float* __restrict__ bc,
                      float* __restrict__ out, int n_graphs, int outc) {
    int tid = blockIdx.x * blockDim.x + threadIdx.x;
    if (tid >= n_graphs * outc) return;
    int g = tid / outc, o = tid % outc;
    float inv = 1.0f / fmaxf(g_cnt[g], 1.0f);
    float s = 0.0f;
    #pragma unroll
    for (int k = 0; k < HID; k++)
        s += g_pool[g * HID + k] * inv * Wc[k * outc + o];
    out[g * outc + o] = s + bc[o];
}

// ---------------- launch ---------------------------------------------------------
extern "C" void kernel_launch(void* const* d_in, const int* in_sizes, int n_in,
                              void* d_out, int out_size) {
    const float* x   = (const float*)d_in[0];
    const int*   ei  = (const int*)d_in[1];     // [2, E] int32
    const int*   bat = (const int*)d_in[2];     // [N]    int32
    const float* W1  = (const float*)d_in[3];
    const float* b1  = (const float*)d_in[4];
    const float* W2  = (const float*)d_in[5];
    const float* b2  = (const float*)d_in[6];
    const float* Wc  = (const float*)d_in[7];
    const float* bc  = (const float*)d_in[8];
    float* out = (float*)d_out;

    int n = in_sizes[0] / INCH;        // 50000
    int e = in_sizes[1] / 2;           // 800000
    int outc = 2;
    int ngr = out_size / outc;         // 128

    const int* src = ei;
    const int* dst = ei + e;

    int init_elems = n > GMAX * HID ? n : GMAX * HID;
    k_init<<<(init_elems + 255) / 256, 256>>>(n);
    k_deg <<<(e + 255) / 256, 256>>>(dst, e);
    k_scan<<<1, 1024>>>(n);
    k_fill<<<(e + 255) / 256, 256>>>(src, dst, e);
    k_lin1<<<(n + 3) / 4, 256>>>(x, W1, n);
    k_gather_lin2<<<(n + 4 * GROUPS - 1) / (4 * GROUPS), 256>>>(W2, b1, n);
    k_gather_pool<<<(n + 3) / 4, 256>>>(b2, bat, n);
    k_cls <<<(ngr * outc + 255) / 256, 256>>>(Wc, bc, out, ngr, outc);
}

// round 15
// speedup vs baseline: 1.0111x; 1.0111x over previous
#include <cuda_runtime.h>
#include <cuda_bf16.h>

#define NMAX   50000
#define EMAX   800000
#define HID    64
#define INCH   16
#define GMAX   128

// ---------------- scratch (device globals) ----------------------------------
__device__ __align__(16) int   g_deg [NMAX];
__device__ __align__(16) int   g_off [NMAX + 1];
__device__ __align__(16) int   g_cur [NMAX];
__device__ __align__(16) int   g_csr [EMAX];
__device__ __align__(16) float g_dinv[NMAX];
__device__ __align__(16) float g_hs  [(size_t)NMAX * HID];  // layer-1 feats * dinv[src]
__device__ __align__(16) float g_hs2 [(size_t)NMAX * HID];  // layer-2 feats * dinv[src]
__device__ __align__(16) float g_pool[GMAX * HID];
__device__ __align__(16) float g_cnt [GMAX];

__device__ __forceinline__ void red_add_f(float* p, float v) {
    asm volatile("red.global.add.f32 [%0], %1;" :: "l"(p), "f"(v) : "memory");
}

// ---------------- k0: init ---------------------------------------------------
__global__ void k_init(int n) {
    int i = blockIdx.x * blockDim.x + threadIdx.x;
    if (i < n) g_deg[i] = 0;
    if (i < GMAX * HID) g_pool[i] = 0.0f;
    if (i < GMAX) g_cnt[i] = 0.0f;
}

// ---------------- k1: in-degree histogram ------------------------------------
__global__ void k_deg(const int* __restrict__ dst, int e) {
    int i = blockIdx.x * blockDim.x + threadIdx.x;
    if (i < e) atomicAdd(&g_deg[dst[i]], 1);
}

// ---------------- k2: exclusive scan (single block, 1024 threads) -------------
__global__ void k_scan(int n) {
    __shared__ int part[1024];
    int tid = threadIdx.x;
    int per = (n + 1023) / 1024;
    int start = tid * per;
    int end = start + per; if (end > n) end = n;
    int s = 0;
    for (int i = start; i < end; i++) s += g_deg[i];
    part[tid] = s;
    __syncthreads();
    for (int off = 1; off < 1024; off <<= 1) {
        int v = (tid >= off) ? part[tid - off] : 0;
        __syncthreads();
        part[tid] += v;
        __syncthreads();
    }
    int run = (tid > 0) ? part[tid - 1] : 0;
    for (int i = start; i < end; i++) {
        g_off[i] = run;
        g_cur[i] = run;
        run += g_deg[i];
    }
    if (tid == 1023) g_off[n] = run;
}

// ---------------- k3: CSR fill -------------------------------------------------
__global__ void k_fill(const int* __restrict__ src, const int* __restrict__ dst, int e) {
    int i = blockIdx.x * blockDim.x + threadIdx.x;
    if (i < e) {
        int pos = atomicAdd(&g_cur[dst[i]], 1);
        g_csr[pos] = src[i];
    }
}

// ---------------- k4: dinv + hs = (x@W1)*dinv ---------------------------------
__global__ void k_lin1(const float* __restrict__ x, const float* __restrict__ W1, int n) {
    __shared__ float Ws[INCH * HID];
    __shared__ float xs[4][INCH];
    __shared__ float ds[4];
    int tid = threadIdx.x;
    for (int i = tid; i < INCH * HID; i += 256) Ws[i] = W1[i];
    int node0 = blockIdx.x * 4;
    if (tid < 4 * INCH) {
        int nl = tid >> 4, k = tid & 15;
        int node = node0 + nl;
        xs[nl][k] = (node < n) ? x[(size_t)node * INCH + k] : 0.0f;
    }
    if (tid < 4) {
        int node = node0 + tid;
        float d = 0.0f;
        if (node < n) {
            d = rsqrtf((float)(g_deg[node] + 1));   // +1 self loop
            g_dinv[node] = d;
        }
        ds[tid] = d;
    }
    __syncthreads();
    int nl = tid >> 6, ch = tid & 63;
    int node = node0 + nl;
    if (node < n) {
        float s = 0.0f;
        #pragma unroll
        for (int k = 0; k < INCH; k++) s += xs[nl][k] * Ws[k * HID + ch];
        g_hs[(size_t)node * HID + ch] = s * ds[nl];
    }
}

// ---------------- k5: gather layer1 + relu + @W2 (fused) -----------------------
// block = 256 threads (4 nodes x 64 ch), loops over 8 groups -> 32 nodes/block
#define GROUPS 8
__global__ void k_gather_lin2(const float* __restrict__ W2, const float* __restrict__ b1, int n) {
    __shared__ float Ws[HID * HID];   // 16 KB
    __shared__ float zs[4][HID];
    int tid = threadIdx.x;
    for (int i = tid; i < HID * HID; i += 256) Ws[i] = W2[i];
    int nl = tid >> 6, ch = tid & 63;
    int block0 = blockIdx.x * (4 * GROUPS);
    for (int grp = 0; grp < GROUPS; grp++) {
        int node = block0 + grp * 4 + nl;
        float z = 0.0f;
        if (node < n) {
            int r0 = g_off[node], r1 = g_off[node + 1];
            float a0 = 0.0f, a1 = 0.0f;
            int j = r0;
            for (; j + 1 < r1; j += 2) {
                int s0 = g_csr[j], s1 = g_csr[j + 1];
                a0 += g_hs[(size_t)s0 * HID + ch];
                a1 += g_hs[(size_t)s1 * HID + ch];
            }
            if (j < r1) a0 += g_hs[(size_t)g_csr[j] * HID + ch];
            float agg = a0 + a1 + g_hs[(size_t)node * HID + ch];  // + self loop
            z = fmaxf(agg * g_dinv[node] + b1[ch], 0.0f);
        }
        __syncthreads();
        zs[nl][ch] = z;
        __syncthreads();
        if (node < n) {
            float s = 0.0f;
            #pragma unroll
            for (int k = 0; k < HID; k++) s += zs[nl][k] * Ws[k * HID + ch];
            g_hs2[(size_t)node * HID + ch] = s * g_dinv[node];
        }
    }
}

// ---------------- k6: gather layer2 + relu + pool (fused) ----------------------
__global__ void k_gather_pool(const float* __restrict__ b2,
                              const int* __restrict__ batch, int n) {
    int tid = threadIdx.x;
    int nl = tid >> 6, ch = tid & 63;
    int node = blockIdx.x * 4 + nl;
    if (node >= n) return;
    int r0 = g_off[node], r1 = g_off[node + 1];
    float a0 = 0.0f, a1 = 0.0f;
    int j = r0;
    for (; j + 1 < r1; j += 2) {
        int s0 = g_csr[j], s1 = g_csr[j + 1];
        a0 += g_hs2[(size_t)s0 * HID + ch];
        a1 += g_hs2[(size_t)s1 * HID + ch];
    }
    if (j < r1) a0 += g_hs2[(size_t)g_csr[j] * HID + ch];
    float agg = a0 + a1 + g_hs2[(size_t)node * HID + ch];
    float z = fmaxf(agg * g_dinv[node] + b2[ch], 0.0f);
    int g = __ldg(&batch[node]);
    red_add_f(&g_pool[g * HID + ch], z);
    if (ch == 0) red_add_f(&g_cnt[g], 1.0f);
}

// ---------------- k7: classifier ------------------------------------------------
__global__ void k_cls(const float* __restrict__ Wc, const float* __restrict__ bc,
                      float* __restrict__ out, int n_graphs, int outc) {
    int tid = blockIdx.x * blockDim.x + threadIdx.x;
    if (tid >= n_graphs * outc) return;
    int g = tid / outc, o = tid % outc;
    float inv = 1.0f / fmaxf(g_cnt[g], 1.0f);
    float s = 0.0f;
    #pragma unroll
    for (int k = 0; k < HID; k++)
        s += g_pool[g * HID + k] * inv * Wc[k * outc + o];
    out[g * outc + o] = s + bc[o];
}

// ---------------- launch ---------------------------------------------------------
extern "C" void kernel_launch(void* const* d_in, const int* in_sizes, int n_in,
                              void* d_out, int out_size) {
    const float* x   = (const float*)d_in[0];
    const int*   ei  = (const int*)d_in[1];     // [2, E] int32
    const int*   bat = (const int*)d_in[2];     // [N]    int32
    const float* W1  = (const float*)d_in[3];
    const float* b1  = (const float*)d_in[4];
    const float* W2  = (const float*)d_in[5];
    const float* b2  = (const float*)d_in[6];
    const float* Wc  = (const float*)d_in[7];
    const float* bc  = (const float*)d_in[8];
    float* out = (float*)d_out;

    int n = in_sizes[0] / INCH;        // 50000
    int e = in_sizes[1] / 2;           // 800000
    int outc = 2;
    int ngr = out_size / outc;         // 128

    const int* src = ei;
    const int* dst = ei + e;

    int init_elems = n > GMAX * HID ? n : GMAX * HID;
    k_init<<<(init_elems + 255) / 256, 256>>>(n);
    k_deg <<<(e + 255) / 256, 256>>>(dst, e);
    k_scan<<<1, 1024>>>(n);
    k_fill<<<(e + 255) / 256, 256>>>(src, dst, e);
    k_lin1<<<(n + 3) / 4, 256>>>(x, W1, n);
    k_gather_lin2<<<(n + 4 * GROUPS - 1) / (4 * GROUPS), 256>>>(W2, b1, n);
    k_gather_pool<<<(n + 3) / 4, 256>>>(b2, bat, n);
    k_cls <<<(ngr * outc + 255) / 256, 256>>>(Wc, bc, out, ngr, outc);
}